// round 14
// baseline (speedup 1.0000x reference)
#include <cuda_runtime.h>
#include <math.h>

#define Bn   128
#define N1n  128
#define N2n  384
#define Nn   512
#define En   1024
#define DIN  64
#define DFC  128
#define NCHUNK 16
#define ROWS_PER_CHUNK (Nn / NCHUNK)   // 32

// ---------------- device scratch (no allocations allowed) ----------------
__device__ float g_colP[8 * Bn * N2n];       // partial col sumsq (8 slices)
__device__ float g_rcpRow[Bn * N1n];
__device__ int   g_am[Bn * N1n];
__device__ float g_topP[Bn * NCHUNK];
__device__ float g_botP[Bn * NCHUNK];
__device__ float g_rmsd[Bn];
__device__ float g_cen[Bn];
__device__ float g_pair[Bn];

// ---------------- helpers ----------------
template<int NV>
__device__ __forceinline__ void bsumN(float* v, float (*sw)[NV]) {
    int t = threadIdx.x, lane = t & 31, w = t >> 5;   // 8 warps
    #pragma unroll
    for (int o = 16; o; o >>= 1) {
        #pragma unroll
        for (int k = 0; k < NV; k++) v[k] += __shfl_xor_sync(0xffffffffu, v[k], o);
    }
    if (lane == 0) {
        #pragma unroll
        for (int k = 0; k < NV; k++) sw[w][k] = v[k];
    }
    __syncthreads();
    #pragma unroll
    for (int k = 0; k < NV; k++) {
        float s = 0.f;
        #pragma unroll
        for (int ww = 0; ww < 8; ww++) s += sw[ww][k];
        v[k] = s;
    }
    __syncthreads();
}

// ---------------- kernel 1: norms + argmax (float4-vectorized) ----------
__global__ __launch_bounds__(256, 8)
void k_prep(const float* __restrict__ att) {
    int b = blockIdx.x;
    int part = blockIdx.y;             // 0..7
    int t = threadIdx.x;               // 256 threads = 8 warps
    int w = t >> 5, lane = t & 31;
    const float* ab = att + (size_t)b * N1n * N2n;

    if (part < 4) {
        // rows [part*32, +32): warp per row, 4 rows/warp, float4 loads
        #pragma unroll
        for (int r = 0; r < 4; r++) {
            int j = part * 32 + w * 4 + r;
            const float4* row = (const float4*)(ab + (size_t)j * N2n);
            float s = 0.f;
            float mx = -1e30f; int am = 0;
            #pragma unroll
            for (int kk = 0; kk < 3; kk++) {
                float4 v = __ldg(&row[kk * 32 + lane]);
                int k0 = (kk * 32 + lane) * 4;
                s = fmaf(v.x, v.x, s); s = fmaf(v.y, v.y, s);
                s = fmaf(v.z, v.z, s); s = fmaf(v.w, v.w, s);
                if (v.x > mx) { mx = v.x; am = k0 + 0; }
                if (v.y > mx) { mx = v.y; am = k0 + 1; }
                if (v.z > mx) { mx = v.z; am = k0 + 2; }
                if (v.w > mx) { mx = v.w; am = k0 + 3; }
            }
            #pragma unroll
            for (int o = 16; o; o >>= 1) {
                s += __shfl_xor_sync(0xffffffffu, s, o);
                float omx = __shfl_xor_sync(0xffffffffu, mx, o);
                int   oam = __shfl_xor_sync(0xffffffffu, am, o);
                if (omx > mx || (omx == mx && oam < am)) { mx = omx; am = oam; }
            }
            if (lane == 0) {
                g_rcpRow[b * N1n + j] = 1.0f / fmaxf(sqrtf(s), 1e-12f);
                g_am[b * N1n + j] = am;
            }
        }
    } else {
        // col partials over rows [(part-4)*32, +32): 2 groups x 16 rows
        int rp = part - 4;
        if (t < 192) {
            int g = t / 96;            // 0 or 1
            int c4 = t % 96;           // f4 column
            const float4* base = (const float4*)(ab + (size_t)(rp * 32 + g * 16) * N2n);
            float4 a0 = make_float4(0.f, 0.f, 0.f, 0.f);
            float4 a1 = make_float4(0.f, 0.f, 0.f, 0.f);
            #pragma unroll
            for (int i = 0; i < 16; i += 2) {
                float4 v0 = __ldg(&base[(size_t)(i + 0) * 96 + c4]);
                float4 v1 = __ldg(&base[(size_t)(i + 1) * 96 + c4]);
                a0.x = fmaf(v0.x, v0.x, a0.x); a0.y = fmaf(v0.y, v0.y, a0.y);
                a0.z = fmaf(v0.z, v0.z, a0.z); a0.w = fmaf(v0.w, v0.w, a0.w);
                a1.x = fmaf(v1.x, v1.x, a1.x); a1.y = fmaf(v1.y, v1.y, a1.y);
                a1.z = fmaf(v1.z, v1.z, a1.z); a1.w = fmaf(v1.w, v1.w, a1.w);
            }
            float4 out;
            out.x = a0.x + a1.x; out.y = a0.y + a1.y;
            out.z = a0.z + a1.z; out.w = a0.w + a1.w;
            ((float4*)(g_colP + ((rp * 2 + g) * Bn + b) * N2n))[c4] = out;
        }
    }
}

// ---------------- role bodies for the fused kernel ----------------------
__device__ void body_loss(int b, int chunk,
                          const float* __restrict__ att,
                          const float* __restrict__ mapping,
                          const float* __restrict__ samelb) {
    int t = threadIdx.x;               // 256 threads
    int rl = t >> 7;
    int j4 = t & 127;

    __shared__ float sRcpCol[N2n];
    __shared__ float sRcpRow[N1n];
    for (int idx = t; idx < N2n; idx += 256) {
        float s = 0.f;
        #pragma unroll
        for (int p = 0; p < 8; p++)
            s += g_colP[(p * Bn + b) * N2n + idx];
        sRcpCol[idx] = 1.0f / fmaxf(sqrtf(s), 1e-12f);
    }
    if (t < N1n) sRcpRow[t] = g_rcpRow[b * N1n + t];
    __syncthreads();

    float top = 0.f, bot = 0.f;
    const float4* mp = (const float4*)(mapping + (size_t)b * Nn * Nn);
    const float4* sl = (const float4*)(samelb + (size_t)b * Nn * Nn);

    for (int ii = 0; ii < ROWS_PER_CHUNK; ii += 2) {
        int i = chunk * ROWS_PER_CHUNK + ii + rl;
        float4 m = __ldcs(&mp[(size_t)i * 128 + j4]);
        float4 s = __ldcs(&sl[(size_t)i * 128 + j4]);
        float4 e;
        if (i < N1n) {
            if (j4 >= 32) {
                const float4* ar = (const float4*)(att + ((size_t)b * N1n + i) * N2n);
                float4 av = __ldg(&ar[j4 - 32]);
                int c0 = (j4 - 32) * 4;
                e.x = __expf(-av.x * sRcpCol[c0 + 0]);
                e.y = __expf(-av.y * sRcpCol[c0 + 1]);
                e.z = __expf(-av.z * sRcpCol[c0 + 2]);
                e.w = __expf(-av.w * sRcpCol[c0 + 3]);
            } else {
                e = make_float4(1.f, 1.f, 1.f, 1.f);
            }
        } else {
            if (j4 < 32) {
                int col = i - N1n;
                int j = j4 * 4;
                const float* abase = att + (size_t)b * N1n * N2n + col;
                float a0 = __ldg(abase + (size_t)(j + 0) * N2n);
                float a1 = __ldg(abase + (size_t)(j + 1) * N2n);
                float a2 = __ldg(abase + (size_t)(j + 2) * N2n);
                float a3 = __ldg(abase + (size_t)(j + 3) * N2n);
                e.x = __expf(-a0 * sRcpRow[j + 0]);
                e.y = __expf(-a1 * sRcpRow[j + 1]);
                e.z = __expf(-a2 * sRcpRow[j + 2]);
                e.w = __expf(-a3 * sRcpRow[j + 3]);
            } else {
                e = make_float4(1.f, 1.f, 1.f, 1.f);
            }
        }
        top = fmaf(m.x, e.x, top); top = fmaf(m.y, e.y, top);
        top = fmaf(m.z, e.z, top); top = fmaf(m.w, e.w, top);
        bot = fmaf(s.x, e.x, bot); bot = fmaf(s.y, e.y, bot);
        bot = fmaf(s.z, e.z, bot); bot = fmaf(s.w, e.w, bot);
    }

    __shared__ float rt[256], rb[256];
    rt[t] = top; rb[t] = bot; __syncthreads();
    #pragma unroll
    for (int sft = 128; sft > 0; sft >>= 1) {
        if (t < sft) { rt[t] += rt[t + sft]; rb[t] += rb[t + sft]; }
        __syncthreads();
    }
    if (t == 0) {
        g_topP[b * NCHUNK + chunk] = rt[0];
        g_botP[b * NCHUNK + chunk] = rb[0];
    }
}

__device__ void body_kabsch(int b,
                            const float* __restrict__ coords,
                            const float* __restrict__ upd,
                            const float* __restrict__ nm) {
    int t = threadIdx.x;               // 256 threads; rows on t<128
    __shared__ float sw9[8][9];
    __shared__ float sh[12];
    bool act = t < N1n;

    float px = 0.f, py = 0.f, pz = 0.f, qx = 0.f, qy = 0.f, qz = 0.f;
    if (act) {
        int am = g_am[b * N1n + t];
        const float* pu = upd + ((size_t)b * Nn + t) * 3;
        px = pu[0]; py = pu[1]; pz = pu[2];
        const float* qc = coords + ((size_t)b * Nn + N1n + am) * 3;
        qx = qc[0]; qy = qc[1]; qz = qc[2];
    }

    float v6[9] = {px, py, pz, qx, qy, qz, 0.f, 0.f, 0.f};
    bsumN<9>(v6, sw9);
    float pmx = v6[0] * (1.f / 128.f), pmy = v6[1] * (1.f / 128.f), pmz = v6[2] * (1.f / 128.f);
    float qmx = v6[3] * (1.f / 128.f), qmy = v6[4] * (1.f / 128.f), qmz = v6[5] * (1.f / 128.f);

    float cx = px - pmx, cy = py - pmy, cz = pz - pmz;
    float dx = qx - qmx, dy = qy - qmy, dz = qz - qmz;
    float hv[9];
    if (act) {
        hv[0] = cx * dx; hv[1] = cx * dy; hv[2] = cx * dz;
        hv[3] = cy * dx; hv[4] = cy * dy; hv[5] = cy * dz;
        hv[6] = cz * dx; hv[7] = cz * dy; hv[8] = cz * dz;
    } else {
        #pragma unroll
        for (int k = 0; k < 9; k++) hv[k] = 0.f;
    }
    bsumN<9>(hv, sw9);

    if (t == 0) {
        float H[3][3] = {{hv[0] * 0.125f, hv[1] * 0.125f, hv[2] * 0.125f},
                         {hv[3] * 0.125f, hv[4] * 0.125f, hv[5] * 0.125f},
                         {hv[6] * 0.125f, hv[7] * 0.125f, hv[8] * 0.125f}};
        float K[3][3];
        #pragma unroll
        for (int a = 0; a < 3; a++)
            #pragma unroll
            for (int c = 0; c < 3; c++) {
                float s = 0;
                #pragma unroll
                for (int r = 0; r < 3; r++) s += H[r][a] * H[r][c];
                K[a][c] = s;
            }
        float V[3][3] = {{1, 0, 0}, {0, 1, 0}, {0, 0, 1}};
        for (int sweep = 0; sweep < 8; sweep++) {
            #pragma unroll
            for (int pi = 0; pi < 3; pi++) {
                int p = (pi == 2) ? 1 : 0;
                int q = (pi == 0) ? 1 : 2;
                float apq = K[p][q];
                if (fabsf(apq) < 1e-30f) continue;
                float theta = (K[q][q] - K[p][p]) / (2.0f * apq);
                float tt = copysignf(1.0f, theta) / (fabsf(theta) + sqrtf(theta * theta + 1.0f));
                float c = rsqrtf(tt * tt + 1.0f);
                float s = tt * c;
                #pragma unroll
                for (int r = 0; r < 3; r++) {
                    float kp = K[p][r], kq = K[q][r];
                    K[p][r] = c * kp - s * kq;
                    K[q][r] = s * kp + c * kq;
                }
                #pragma unroll
                for (int r = 0; r < 3; r++) {
                    float kp = K[r][p], kq = K[r][q];
                    K[r][p] = c * kp - s * kq;
                    K[r][q] = s * kp + c * kq;
                    float vp = V[r][p], vq = V[r][q];
                    V[r][p] = c * vp - s * vq;
                    V[r][q] = s * vp + c * vq;
                }
            }
        }
        float lam[3] = {K[0][0], K[1][1], K[2][2]};
        #pragma unroll
        for (int a = 0; a < 2; a++)
            #pragma unroll
            for (int c = a + 1; c < 3; c++)
                if (lam[c] > lam[a]) {
                    float tmp = lam[a]; lam[a] = lam[c]; lam[c] = tmp;
                    #pragma unroll
                    for (int r = 0; r < 3; r++) {
                        float tv = V[r][a]; V[r][a] = V[r][c]; V[r][c] = tv;
                    }
                }
        float s0 = fmaxf(sqrtf(fmaxf(lam[0], 0.f)), 1e-20f);
        float s1 = fmaxf(sqrtf(fmaxf(lam[1], 0.f)), 1e-20f);
        float s2 = fmaxf(sqrtf(fmaxf(lam[2], 0.f)), 1e-20f);
        float det = H[0][0] * (H[1][1] * H[2][2] - H[1][2] * H[2][1])
                  - H[0][1] * (H[1][0] * H[2][2] - H[1][2] * H[2][0])
                  + H[0][2] * (H[1][0] * H[2][1] - H[1][1] * H[2][0]);
        float d = (det > 0.f) ? 1.f : ((det < 0.f) ? -1.f : 0.f);
        float g[3] = {1.0f / s0, 1.0f / s1, d / s2};
        float M[3][3];
        #pragma unroll
        for (int a = 0; a < 3; a++)
            #pragma unroll
            for (int c = 0; c < 3; c++)
                M[a][c] = V[a][0] * g[0] * V[c][0] + V[a][1] * g[1] * V[c][1] + V[a][2] * g[2] * V[c][2];
        float R[3][3];
        #pragma unroll
        for (int a = 0; a < 3; a++)
            #pragma unroll
            for (int c = 0; c < 3; c++)
                R[a][c] = H[a][0] * M[0][c] + H[a][1] * M[1][c] + H[a][2] * M[2][c];
        float Pm[3] = {pmx, pmy, pmz};
        float Qm[3] = {qmx, qmy, qmz};
        #pragma unroll
        for (int a = 0; a < 3; a++) {
            sh[a * 3 + 0] = R[a][0];
            sh[a * 3 + 1] = R[a][1];
            sh[a * 3 + 2] = R[a][2];
            sh[9 + a] = Qm[a] - (R[a][0] * Pm[0] + R[a][1] * Pm[1] + R[a][2] * Pm[2]);
        }
    }
    __syncthreads();

    float fv[9] = {0.f, 0.f, 0.f, 0.f, 0.f, 0.f, 0.f, 0.f, 0.f};
    if (act) {
        float ppx = sh[0] * px + sh[1] * py + sh[2] * pz + sh[9];
        float ppy = sh[3] * px + sh[4] * py + sh[5] * pz + sh[10];
        float ppz = sh[6] * px + sh[7] * py + sh[8] * pz + sh[11];
        float mk = (nm[b * N1n + t] > 0.5f) ? 1.f : 0.f;
        float ex = ppx - qx, ey = ppy - qy, ez = ppz - qz;
        fv[0] = mk * (ex * ex + ey * ey + ez * ez);
        fv[1] = mk;
        fv[2] = ppx; fv[3] = ppy; fv[4] = ppz;
    }
    __syncthreads();
    bsumN<9>(fv, sw9);
    if (t == 0) {
        float cc = fmaxf(fv[1] * 3.0f, 1.0f);
        g_rmsd[b] = fv[0] / cc;
        float gx = fv[2] * (1.f / 128.f) - qmx;
        float gy = fv[3] * (1.f / 128.f) - qmy;
        float gz = fv[4] * (1.f / 128.f) - qmz;
        g_cen[b] = (gx * gx + gy * gy + gz * gz) * (1.f / 3.f);
    }
}

__device__ void body_pair(int b,
                          const float* __restrict__ coords,
                          const float* __restrict__ upd,
                          const int* __restrict__ edge) {
    int t = threadIdx.x;               // 256 threads
    __shared__ float red[256];
    const float* cb = coords + (size_t)b * Nn * 3;
    const float* ub = upd + (size_t)b * Nn * 3;
    const int* eb = edge + (size_t)b * En * 2;
    float acc = 0.f;
    for (int e = t; e < En; e += 256) {
        int i0 = eb[e * 2], i1 = eb[e * 2 + 1];
        float ax = cb[i0 * 3] - cb[i1 * 3];
        float ay = cb[i0 * 3 + 1] - cb[i1 * 3 + 1];
        float az = cb[i0 * 3 + 2] - cb[i1 * 3 + 2];
        float d0 = sqrtf(ax * ax + ay * ay + az * az + 1e-12f);
        float bx = ub[i0 * 3] - ub[i1 * 3];
        float by = ub[i0 * 3 + 1] - ub[i1 * 3 + 1];
        float bz = ub[i0 * 3 + 2] - ub[i1 * 3 + 2];
        float d1 = sqrtf(bx * bx + by * by + bz * bz + 1e-12f);
        acc += (d1 - d0);
    }
    red[t] = acc; __syncthreads();
    #pragma unroll
    for (int s = 128; s > 0; s >>= 1) {
        if (t < s) red[t] += red[t + s];
        __syncthreads();
    }
    if (t == 0) g_pair[b] = fabsf(red[0]);
    __syncthreads();
}

__device__ void body_mlp(int b,
                         const float* __restrict__ c_hs,
                         const float* __restrict__ c_valid,
                         const float* __restrict__ W0, const float* __restrict__ b0,
                         const float* __restrict__ W1, const float* __restrict__ b1,
                         const float* __restrict__ W2, const float* __restrict__ b2,
                         const float* __restrict__ W3, const float* __restrict__ b3,
                         float* __restrict__ out) {
    int t = threadIdx.x;               // 256 threads; layers on t<128
    __shared__ float pooled[DIN];
    __shared__ float h1[DFC];
    __shared__ float h2s[DFC];
    __shared__ float red[256];

    int d = t & 63, q = t >> 6;        // 4-way over rows
    float acc = 0.f;
    const float* base = c_hs + (size_t)b * Nn * DIN;
    const float* cv = c_valid + (size_t)b * Nn;
    #pragma unroll 4
    for (int n = q; n < Nn; n += 4)
        acc = fmaf(base[(size_t)n * DIN + d], cv[n], acc);
    red[t] = acc; __syncthreads();
    if (t < 64) pooled[t] = (red[t] + red[t + 64] + red[t + 128] + red[t + 192]) * (1.0f / 128.0f);
    __syncthreads();

    float a = 0.f;
    if (t < DFC) {
        a = b0[t];
        #pragma unroll 8
        for (int k = 0; k < DIN; k++) a = fmaf(pooled[k], W0[k * DFC + t], a);
        h1[t] = fmaxf(a, 0.f);
    }
    __syncthreads();
    if (t < DFC) {
        a = b1[t];
        #pragma unroll 8
        for (int k = 0; k < DFC; k++) a = fmaf(h1[k], W1[k * DFC + t], a);
        h2s[t] = fmaxf(a, 0.f);
    }
    __syncthreads();
    float contrib = 0.f;
    if (t < DFC) {
        a = b2[t];
        #pragma unroll 8
        for (int k = 0; k < DFC; k++) a = fmaf(h2s[k], W2[k * DFC + t], a);
        contrib = fmaxf(a, 0.f) * W3[t];
    }
    red[t] = contrib;
    __syncthreads();
    #pragma unroll
    for (int s = 128; s > 0; s >>= 1) {
        if (t < s) red[t] += red[t + s];
        __syncthreads();
    }
    if (t == 0) out[b] = 1.0f / (1.0f + expf(-(red[0] + b3[0])));
}

// ---------------- kernel 2: big fused kernel (18 roles = <2 waves) ------
__global__ __launch_bounds__(256, 8)
void k_fused(const float* __restrict__ att,
             const float* __restrict__ mapping,
             const float* __restrict__ samelb,
             const float* __restrict__ coords,
             const float* __restrict__ upd,
             const float* __restrict__ nm,
             const int* __restrict__ edge,
             const float* __restrict__ c_hs,
             const float* __restrict__ c_valid,
             const float* __restrict__ W0, const float* __restrict__ b0,
             const float* __restrict__ W1, const float* __restrict__ b1,
             const float* __restrict__ W2, const float* __restrict__ b2,
             const float* __restrict__ W3, const float* __restrict__ b3,
             float* __restrict__ out) {
    int role = blockIdx.x;
    int b = blockIdx.y;
    if (role < NCHUNK) {
        body_loss(b, role, att, mapping, samelb);
    } else if (role == NCHUNK) {
        body_kabsch(b, coords, upd, nm);
    } else {
        body_pair(b, coords, upd, edge);
        body_mlp(b, c_hs, c_valid, W0, b0, W1, b1, W2, b2, W3, b3, out);
    }
}

// ---------------- kernel 3: finalize scalars ----------------------------
__global__ void k_final(float* __restrict__ out) {
    int t = threadIdx.x;                // 128 threads, t = batch
    int lane = t & 31, w = t >> 5;
    float top = 0.f, bot = 0.f;
    #pragma unroll
    for (int c = 0; c < NCHUNK; c++) {
        top += g_topP[t * NCHUNK + c];
        bot += g_botP[t * NCHUNK + c];
    }
    float vals[4] = {top / (bot - top + 1.0f), g_rmsd[t], g_pair[t], g_cen[t]};
    __shared__ float sw4[4][4];
    #pragma unroll
    for (int o = 16; o; o >>= 1)
        #pragma unroll
        for (int k = 0; k < 4; k++) vals[k] += __shfl_xor_sync(0xffffffffu, vals[k], o);
    if (lane == 0)
        #pragma unroll
        for (int k = 0; k < 4; k++) sw4[w][k] = vals[k];
    __syncthreads();
    if (t == 0) {
        #pragma unroll
        for (int k = 0; k < 4; k++) {
            float s = sw4[0][k] + sw4[1][k] + sw4[2][k] + sw4[3][k];
            out[128 + k] = s * (1.f / 128.f);
        }
    }
}

// ---------------- launch ----------------
extern "C" void kernel_launch(void* const* d_in, const int* in_sizes, int n_in,
                              void* d_out, int out_size) {
    const float* c_hs      = (const float*)d_in[0];
    const float* attention = (const float*)d_in[1];
    const float* coords    = (const float*)d_in[2];
    const float* upd       = (const float*)d_in[3];
    const float* c_valid   = (const float*)d_in[4];
    const float* nm        = (const float*)d_in[5];
    const float* mapping   = (const float*)d_in[6];
    const float* samelb    = (const float*)d_in[7];
    const int*   edge      = (const int*)d_in[8];
    const float* W0 = (const float*)d_in[9];
    const float* b0 = (const float*)d_in[10];
    const float* W1 = (const float*)d_in[11];
    const float* b1 = (const float*)d_in[12];
    const float* W2 = (const float*)d_in[13];
    const float* b2 = (const float*)d_in[14];
    const float* W3 = (const float*)d_in[15];
    const float* b3 = (const float*)d_in[16];
    float* out = (float*)d_out;

    k_prep<<<dim3(Bn, 8), 256>>>(attention);
    k_fused<<<dim3(NCHUNK + 2, Bn), 256>>>(attention, mapping, samelb,
                                           coords, upd, nm, edge, c_hs, c_valid,
                                           W0, b0, W1, b1, W2, b2, W3, b3, out);
    k_final<<<1, 128>>>(out);
}

// round 16
// speedup vs baseline: 1.0917x; 1.0917x over previous
#include <cuda_runtime.h>
#include <math.h>

#define Bn   128
#define N1n  128
#define N2n  384
#define Nn   512
#define En   1024
#define DIN  64
#define DFC  128
#define NCHUNK 16
#define ROWS_PER_CHUNK (Nn / NCHUNK)   // 32

// ---------------- device scratch (no allocations allowed) ----------------
__device__ float g_colP[8 * Bn * N2n];       // partial col sumsq (8 slices)
__device__ float g_rcpRow[Bn * N1n];
__device__ int   g_am[Bn * N1n];
__device__ float g_topP[Bn * NCHUNK];
__device__ float g_botP[Bn * NCHUNK];
__device__ float g_rmsd[Bn];
__device__ float g_cen[Bn];
__device__ float g_pair[Bn];

// ---------------- helpers ----------------
template<int NV>
__device__ __forceinline__ void bsumN(float* v, float (*sw)[NV]) {
    int t = threadIdx.x, lane = t & 31, w = t >> 5;   // 8 warps
    #pragma unroll
    for (int o = 16; o; o >>= 1) {
        #pragma unroll
        for (int k = 0; k < NV; k++) v[k] += __shfl_xor_sync(0xffffffffu, v[k], o);
    }
    if (lane == 0) {
        #pragma unroll
        for (int k = 0; k < NV; k++) sw[w][k] = v[k];
    }
    __syncthreads();
    #pragma unroll
    for (int k = 0; k < NV; k++) {
        float s = 0.f;
        #pragma unroll
        for (int ww = 0; ww < 8; ww++) s += sw[ww][k];
        v[k] = s;
    }
    __syncthreads();
}

// ---------------- kernel 1: norms + argmax (float4-vectorized) ----------
__global__ __launch_bounds__(256, 8)
void k_prep(const float* __restrict__ att) {
    int b = blockIdx.x;
    int part = blockIdx.y;             // 0..7
    int t = threadIdx.x;               // 256 threads = 8 warps
    int w = t >> 5, lane = t & 31;
    const float* ab = att + (size_t)b * N1n * N2n;

    if (part < 4) {
        // rows [part*32, +32): warp per row, 4 rows/warp, float4 loads
        #pragma unroll
        for (int r = 0; r < 4; r++) {
            int j = part * 32 + w * 4 + r;
            const float4* row = (const float4*)(ab + (size_t)j * N2n);
            float s = 0.f;
            float mx = -1e30f; int am = 0;
            #pragma unroll
            for (int kk = 0; kk < 3; kk++) {
                float4 v = __ldg(&row[kk * 32 + lane]);
                int k0 = (kk * 32 + lane) * 4;
                s = fmaf(v.x, v.x, s); s = fmaf(v.y, v.y, s);
                s = fmaf(v.z, v.z, s); s = fmaf(v.w, v.w, s);
                if (v.x > mx) { mx = v.x; am = k0 + 0; }
                if (v.y > mx) { mx = v.y; am = k0 + 1; }
                if (v.z > mx) { mx = v.z; am = k0 + 2; }
                if (v.w > mx) { mx = v.w; am = k0 + 3; }
            }
            #pragma unroll
            for (int o = 16; o; o >>= 1) {
                s += __shfl_xor_sync(0xffffffffu, s, o);
                float omx = __shfl_xor_sync(0xffffffffu, mx, o);
                int   oam = __shfl_xor_sync(0xffffffffu, am, o);
                if (omx > mx || (omx == mx && oam < am)) { mx = omx; am = oam; }
            }
            if (lane == 0) {
                g_rcpRow[b * N1n + j] = 1.0f / fmaxf(sqrtf(s), 1e-12f);
                g_am[b * N1n + j] = am;
            }
        }
    } else {
        // col partials over rows [(part-4)*32, +32): 2 groups x 16 rows
        int rp = part - 4;
        if (t < 192) {
            int g = t / 96;            // 0 or 1
            int c4 = t % 96;           // f4 column
            const float4* base = (const float4*)(ab + (size_t)(rp * 32 + g * 16) * N2n);
            float4 a0 = make_float4(0.f, 0.f, 0.f, 0.f);
            float4 a1 = make_float4(0.f, 0.f, 0.f, 0.f);
            #pragma unroll
            for (int i = 0; i < 16; i += 2) {
                float4 v0 = __ldg(&base[(size_t)(i + 0) * 96 + c4]);
                float4 v1 = __ldg(&base[(size_t)(i + 1) * 96 + c4]);
                a0.x = fmaf(v0.x, v0.x, a0.x); a0.y = fmaf(v0.y, v0.y, a0.y);
                a0.z = fmaf(v0.z, v0.z, a0.z); a0.w = fmaf(v0.w, v0.w, a0.w);
                a1.x = fmaf(v1.x, v1.x, a1.x); a1.y = fmaf(v1.y, v1.y, a1.y);
                a1.z = fmaf(v1.z, v1.z, a1.z); a1.w = fmaf(v1.w, v1.w, a1.w);
            }
            float4 out;
            out.x = a0.x + a1.x; out.y = a0.y + a1.y;
            out.z = a0.z + a1.z; out.w = a0.w + a1.w;
            ((float4*)(g_colP + ((rp * 2 + g) * Bn + b) * N2n))[c4] = out;
        }
    }
}

// ---------------- role bodies for the fused kernel ----------------------
__device__ void body_loss(int b, int chunk,
                          const float* __restrict__ att,
                          const float* __restrict__ mapping,
                          const float* __restrict__ samelb) {
    int t = threadIdx.x;               // 256 threads
    int rl = t >> 7;
    int j4 = t & 127;

    __shared__ float sNorm[N2n];       // rcpCol (chunks 0-3) or rcpRow (4-15)
    bool topRegion = (chunk < 4);
    if (topRegion) {
        for (int idx = t; idx < N2n; idx += 256) {
            float s = 0.f;
            #pragma unroll
            for (int p = 0; p < 8; p++)
                s += g_colP[(p * Bn + b) * N2n + idx];
            sNorm[idx] = 1.0f / fmaxf(sqrtf(s), 1e-12f);
        }
    } else {
        if (t < N1n) sNorm[t] = g_rcpRow[b * N1n + t];
    }
    __syncthreads();

    float top = 0.f, bot = 0.f;
    const float4* mp = (const float4*)(mapping + (size_t)b * Nn * Nn);
    const float4* sl = (const float4*)(samelb + (size_t)b * Nn * Nn);

    if (topRegion) {
        for (int ii = 0; ii < ROWS_PER_CHUNK; ii += 2) {
            int i = chunk * ROWS_PER_CHUNK + ii + rl;
            // rotate the strip so every warp alternates exp/pure work
            int j4e = (j4 + (ii >> 1) * 32) & 127;
            float4 m = __ldcs(&mp[(size_t)i * 128 + j4e]);
            float4 s = __ldcs(&sl[(size_t)i * 128 + j4e]);
            float4 e;
            if (j4e >= 32) {
                const float4* ar = (const float4*)(att + ((size_t)b * N1n + i) * N2n);
                float4 av = __ldg(&ar[j4e - 32]);
                int c0 = (j4e - 32) * 4;
                e.x = __expf(-av.x * sNorm[c0 + 0]);
                e.y = __expf(-av.y * sNorm[c0 + 1]);
                e.z = __expf(-av.z * sNorm[c0 + 2]);
                e.w = __expf(-av.w * sNorm[c0 + 3]);
            } else {
                e = make_float4(1.f, 1.f, 1.f, 1.f);
            }
            top = fmaf(m.x, e.x, top); top = fmaf(m.y, e.y, top);
            top = fmaf(m.z, e.z, top); top = fmaf(m.w, e.w, top);
            bot = fmaf(s.x, e.x, bot); bot = fmaf(s.y, e.y, bot);
            bot = fmaf(s.z, e.z, bot); bot = fmaf(s.w, e.w, bot);
        }
    } else {
        for (int ii = 0; ii < ROWS_PER_CHUNK; ii += 2) {
            int i = chunk * ROWS_PER_CHUNK + ii + rl;
            int j4e = (j4 + (ii >> 1) * 32) & 127;
            float4 m = __ldcs(&mp[(size_t)i * 128 + j4e]);
            float4 s = __ldcs(&sl[(size_t)i * 128 + j4e]);
            float4 e;
            if (j4e < 32) {
                int col = i - N1n;
                int j = j4e * 4;
                const float* abase = att + (size_t)b * N1n * N2n + col;
                float a0 = __ldg(abase + (size_t)(j + 0) * N2n);
                float a1 = __ldg(abase + (size_t)(j + 1) * N2n);
                float a2 = __ldg(abase + (size_t)(j + 2) * N2n);
                float a3 = __ldg(abase + (size_t)(j + 3) * N2n);
                e.x = __expf(-a0 * sNorm[j + 0]);
                e.y = __expf(-a1 * sNorm[j + 1]);
                e.z = __expf(-a2 * sNorm[j + 2]);
                e.w = __expf(-a3 * sNorm[j + 3]);
            } else {
                e = make_float4(1.f, 1.f, 1.f, 1.f);
            }
            top = fmaf(m.x, e.x, top); top = fmaf(m.y, e.y, top);
            top = fmaf(m.z, e.z, top); top = fmaf(m.w, e.w, top);
            bot = fmaf(s.x, e.x, bot); bot = fmaf(s.y, e.y, bot);
            bot = fmaf(s.z, e.z, bot); bot = fmaf(s.w, e.w, bot);
        }
    }

    __shared__ float rt[256], rb[256];
    rt[t] = top; rb[t] = bot; __syncthreads();
    #pragma unroll
    for (int sft = 128; sft > 0; sft >>= 1) {
        if (t < sft) { rt[t] += rt[t + sft]; rb[t] += rb[t + sft]; }
        __syncthreads();
    }
    if (t == 0) {
        g_topP[b * NCHUNK + chunk] = rt[0];
        g_botP[b * NCHUNK + chunk] = rb[0];
    }
}

__device__ void body_kabsch(int b,
                            const float* __restrict__ coords,
                            const float* __restrict__ upd,
                            const float* __restrict__ nm) {
    int t = threadIdx.x;               // 256 threads; rows on t<128
    __shared__ float sw9[8][9];
    __shared__ float sh[12];
    bool act = t < N1n;

    float px = 0.f, py = 0.f, pz = 0.f, qx = 0.f, qy = 0.f, qz = 0.f;
    if (act) {
        int am = g_am[b * N1n + t];
        const float* pu = upd + ((size_t)b * Nn + t) * 3;
        px = pu[0]; py = pu[1]; pz = pu[2];
        const float* qc = coords + ((size_t)b * Nn + N1n + am) * 3;
        qx = qc[0]; qy = qc[1]; qz = qc[2];
    }

    float v6[9] = {px, py, pz, qx, qy, qz, 0.f, 0.f, 0.f};
    bsumN<9>(v6, sw9);
    float pmx = v6[0] * (1.f / 128.f), pmy = v6[1] * (1.f / 128.f), pmz = v6[2] * (1.f / 128.f);
    float qmx = v6[3] * (1.f / 128.f), qmy = v6[4] * (1.f / 128.f), qmz = v6[5] * (1.f / 128.f);

    float cx = px - pmx, cy = py - pmy, cz = pz - pmz;
    float dx = qx - qmx, dy = qy - qmy, dz = qz - qmz;
    float hv[9];
    if (act) {
        hv[0] = cx * dx; hv[1] = cx * dy; hv[2] = cx * dz;
        hv[3] = cy * dx; hv[4] = cy * dy; hv[5] = cy * dz;
        hv[6] = cz * dx; hv[7] = cz * dy; hv[8] = cz * dz;
    } else {
        #pragma unroll
        for (int k = 0; k < 9; k++) hv[k] = 0.f;
    }
    bsumN<9>(hv, sw9);

    if (t == 0) {
        float H[3][3] = {{hv[0] * 0.125f, hv[1] * 0.125f, hv[2] * 0.125f},
                         {hv[3] * 0.125f, hv[4] * 0.125f, hv[5] * 0.125f},
                         {hv[6] * 0.125f, hv[7] * 0.125f, hv[8] * 0.125f}};
        float K[3][3];
        #pragma unroll
        for (int a = 0; a < 3; a++)
            #pragma unroll
            for (int c = 0; c < 3; c++) {
                float s = 0;
                #pragma unroll
                for (int r = 0; r < 3; r++) s += H[r][a] * H[r][c];
                K[a][c] = s;
            }
        float V[3][3] = {{1, 0, 0}, {0, 1, 0}, {0, 0, 1}};
        for (int sweep = 0; sweep < 8; sweep++) {
            #pragma unroll
            for (int pi = 0; pi < 3; pi++) {
                int p = (pi == 2) ? 1 : 0;
                int q = (pi == 0) ? 1 : 2;
                float apq = K[p][q];
                if (fabsf(apq) < 1e-30f) continue;
                float theta = (K[q][q] - K[p][p]) / (2.0f * apq);
                float tt = copysignf(1.0f, theta) / (fabsf(theta) + sqrtf(theta * theta + 1.0f));
                float c = rsqrtf(tt * tt + 1.0f);
                float s = tt * c;
                #pragma unroll
                for (int r = 0; r < 3; r++) {
                    float kp = K[p][r], kq = K[q][r];
                    K[p][r] = c * kp - s * kq;
                    K[q][r] = s * kp + c * kq;
                }
                #pragma unroll
                for (int r = 0; r < 3; r++) {
                    float kp = K[r][p], kq = K[r][q];
                    K[r][p] = c * kp - s * kq;
                    K[r][q] = s * kp + c * kq;
                    float vp = V[r][p], vq = V[r][q];
                    V[r][p] = c * vp - s * vq;
                    V[r][q] = s * vp + c * vq;
                }
            }
        }
        float lam[3] = {K[0][0], K[1][1], K[2][2]};
        #pragma unroll
        for (int a = 0; a < 2; a++)
            #pragma unroll
            for (int c = a + 1; c < 3; c++)
                if (lam[c] > lam[a]) {
                    float tmp = lam[a]; lam[a] = lam[c]; lam[c] = tmp;
                    #pragma unroll
                    for (int r = 0; r < 3; r++) {
                        float tv = V[r][a]; V[r][a] = V[r][c]; V[r][c] = tv;
                    }
                }
        float s0 = fmaxf(sqrtf(fmaxf(lam[0], 0.f)), 1e-20f);
        float s1 = fmaxf(sqrtf(fmaxf(lam[1], 0.f)), 1e-20f);
        float s2 = fmaxf(sqrtf(fmaxf(lam[2], 0.f)), 1e-20f);
        float det = H[0][0] * (H[1][1] * H[2][2] - H[1][2] * H[2][1])
                  - H[0][1] * (H[1][0] * H[2][2] - H[1][2] * H[2][0])
                  + H[0][2] * (H[1][0] * H[2][1] - H[1][1] * H[2][0]);
        float d = (det > 0.f) ? 1.f : ((det < 0.f) ? -1.f : 0.f);
        float g[3] = {1.0f / s0, 1.0f / s1, d / s2};
        float M[3][3];
        #pragma unroll
        for (int a = 0; a < 3; a++)
            #pragma unroll
            for (int c = 0; c < 3; c++)
                M[a][c] = V[a][0] * g[0] * V[c][0] + V[a][1] * g[1] * V[c][1] + V[a][2] * g[2] * V[c][2];
        float R[3][3];
        #pragma unroll
        for (int a = 0; a < 3; a++)
            #pragma unroll
            for (int c = 0; c < 3; c++)
                R[a][c] = H[a][0] * M[0][c] + H[a][1] * M[1][c] + H[a][2] * M[2][c];
        float Pm[3] = {pmx, pmy, pmz};
        float Qm[3] = {qmx, qmy, qmz};
        #pragma unroll
        for (int a = 0; a < 3; a++) {
            sh[a * 3 + 0] = R[a][0];
            sh[a * 3 + 1] = R[a][1];
            sh[a * 3 + 2] = R[a][2];
            sh[9 + a] = Qm[a] - (R[a][0] * Pm[0] + R[a][1] * Pm[1] + R[a][2] * Pm[2]);
        }
    }
    __syncthreads();

    float fv[9] = {0.f, 0.f, 0.f, 0.f, 0.f, 0.f, 0.f, 0.f, 0.f};
    if (act) {
        float ppx = sh[0] * px + sh[1] * py + sh[2] * pz + sh[9];
        float ppy = sh[3] * px + sh[4] * py + sh[5] * pz + sh[10];
        float ppz = sh[6] * px + sh[7] * py + sh[8] * pz + sh[11];
        float mk = (nm[b * N1n + t] > 0.5f) ? 1.f : 0.f;
        float ex = ppx - qx, ey = ppy - qy, ez = ppz - qz;
        fv[0] = mk * (ex * ex + ey * ey + ez * ez);
        fv[1] = mk;
        fv[2] = ppx; fv[3] = ppy; fv[4] = ppz;
    }
    __syncthreads();
    bsumN<9>(fv, sw9);
    if (t == 0) {
        float cc = fmaxf(fv[1] * 3.0f, 1.0f);
        g_rmsd[b] = fv[0] / cc;
        float gx = fv[2] * (1.f / 128.f) - qmx;
        float gy = fv[3] * (1.f / 128.f) - qmy;
        float gz = fv[4] * (1.f / 128.f) - qmz;
        g_cen[b] = (gx * gx + gy * gy + gz * gz) * (1.f / 3.f);
    }
}

__device__ void body_pair(int b,
                          const float* __restrict__ coords,
                          const float* __restrict__ upd,
                          const int* __restrict__ edge) {
    int t = threadIdx.x;               // 256 threads
    __shared__ float red[256];
    const float* cb = coords + (size_t)b * Nn * 3;
    const float* ub = upd + (size_t)b * Nn * 3;
    const int* eb = edge + (size_t)b * En * 2;
    float acc = 0.f;
    for (int e = t; e < En; e += 256) {
        int i0 = eb[e * 2], i1 = eb[e * 2 + 1];
        float ax = cb[i0 * 3] - cb[i1 * 3];
        float ay = cb[i0 * 3 + 1] - cb[i1 * 3 + 1];
        float az = cb[i0 * 3 + 2] - cb[i1 * 3 + 2];
        float d0 = sqrtf(ax * ax + ay * ay + az * az + 1e-12f);
        float bx = ub[i0 * 3] - ub[i1 * 3];
        float by = ub[i0 * 3 + 1] - ub[i1 * 3 + 1];
        float bz = ub[i0 * 3 + 2] - ub[i1 * 3 + 2];
        float d1 = sqrtf(bx * bx + by * by + bz * bz + 1e-12f);
        acc += (d1 - d0);
    }
    red[t] = acc; __syncthreads();
    #pragma unroll
    for (int s = 128; s > 0; s >>= 1) {
        if (t < s) red[t] += red[t + s];
        __syncthreads();
    }
    if (t == 0) g_pair[b] = fabsf(red[0]);
}

__device__ void body_mlp(int b,
                         const float* __restrict__ c_hs,
                         const float* __restrict__ c_valid,
                         const float* __restrict__ W0, const float* __restrict__ b0,
                         const float* __restrict__ W1, const float* __restrict__ b1,
                         const float* __restrict__ W2, const float* __restrict__ b2,
                         const float* __restrict__ W3, const float* __restrict__ b3,
                         float* __restrict__ out) {
    int t = threadIdx.x;               // 256 threads; layers on t<128
    __shared__ float pooled[DIN];
    __shared__ float h1[DFC];
    __shared__ float h2s[DFC];
    __shared__ float red[256];

    int d = t & 63, q = t >> 6;        // 4-way over rows
    float acc = 0.f;
    const float* base = c_hs + (size_t)b * Nn * DIN;
    const float* cv = c_valid + (size_t)b * Nn;
    #pragma unroll 4
    for (int n = q; n < Nn; n += 4)
        acc = fmaf(base[(size_t)n * DIN + d], cv[n], acc);
    red[t] = acc; __syncthreads();
    if (t < 64) pooled[t] = (red[t] + red[t + 64] + red[t + 128] + red[t + 192]) * (1.0f / 128.0f);
    __syncthreads();

    float a = 0.f;
    if (t < DFC) {
        a = b0[t];
        #pragma unroll 8
        for (int k = 0; k < DIN; k++) a = fmaf(pooled[k], W0[k * DFC + t], a);
        h1[t] = fmaxf(a, 0.f);
    }
    __syncthreads();
    if (t < DFC) {
        a = b1[t];
        #pragma unroll 8
        for (int k = 0; k < DFC; k++) a = fmaf(h1[k], W1[k * DFC + t], a);
        h2s[t] = fmaxf(a, 0.f);
    }
    __syncthreads();
    float contrib = 0.f;
    if (t < DFC) {
        a = b2[t];
        #pragma unroll 8
        for (int k = 0; k < DFC; k++) a = fmaf(h2s[k], W2[k * DFC + t], a);
        contrib = fmaxf(a, 0.f) * W3[t];
    }
    red[t] = contrib;
    __syncthreads();
    #pragma unroll
    for (int s = 128; s > 0; s >>= 1) {
        if (t < s) red[t] += red[t + s];
        __syncthreads();
    }
    if (t == 0) out[b] = 1.0f / (1.0f + expf(-(red[0] + b3[0])));
}

// ---------------- kernel 2: big fused kernel (occupancy 8) --------------
__global__ __launch_bounds__(256, 8)
void k_fused(const float* __restrict__ att,
             const float* __restrict__ mapping,
             const float* __restrict__ samelb,
             const float* __restrict__ coords,
             const float* __restrict__ upd,
             const float* __restrict__ nm,
             const int* __restrict__ edge,
             const float* __restrict__ c_hs,
             const float* __restrict__ c_valid,
             const float* __restrict__ W0, const float* __restrict__ b0,
             const float* __restrict__ W1, const float* __restrict__ b1,
             const float* __restrict__ W2, const float* __restrict__ b2,
             const float* __restrict__ W3, const float* __restrict__ b3,
             float* __restrict__ out) {
    int role = blockIdx.x;
    int b = blockIdx.y;
    if (role < NCHUNK) {
        body_loss(b, role, att, mapping, samelb);
    } else if (role == NCHUNK) {
        body_kabsch(b, coords, upd, nm);
    } else if (role == NCHUNK + 1) {
        body_pair(b, coords, upd, edge);
    } else {
        body_mlp(b, c_hs, c_valid, W0, b0, W1, b1, W2, b2, W3, b3, out);
    }
}

// ---------------- kernel 3: finalize scalars ----------------------------
__global__ void k_final(float* __restrict__ out) {
    int t = threadIdx.x;                // 128 threads, t = batch
    int lane = t & 31, w = t >> 5;
    float top = 0.f, bot = 0.f;
    #pragma unroll
    for (int c = 0; c < NCHUNK; c++) {
        top += g_topP[t * NCHUNK + c];
        bot += g_botP[t * NCHUNK + c];
    }
    float vals[4] = {top / (bot - top + 1.0f), g_rmsd[t], g_pair[t], g_cen[t]};
    __shared__ float sw4[4][4];
    #pragma unroll
    for (int o = 16; o; o >>= 1)
        #pragma unroll
        for (int k = 0; k < 4; k++) vals[k] += __shfl_xor_sync(0xffffffffu, vals[k], o);
    if (lane == 0)
        #pragma unroll
        for (int k = 0; k < 4; k++) sw4[w][k] = vals[k];
    __syncthreads();
    if (t == 0) {
        #pragma unroll
        for (int k = 0; k < 4; k++) {
            float s = sw4[0][k] + sw4[1][k] + sw4[2][k] + sw4[3][k];
            out[128 + k] = s * (1.f / 128.f);
        }
    }
}

// ---------------- launch ----------------
extern "C" void kernel_launch(void* const* d_in, const int* in_sizes, int n_in,
                              void* d_out, int out_size) {
    const float* c_hs      = (const float*)d_in[0];
    const float* attention = (const float*)d_in[1];
    const float* coords    = (const float*)d_in[2];
    const float* upd       = (const float*)d_in[3];
    const float* c_valid   = (const float*)d_in[4];
    const float* nm        = (const float*)d_in[5];
    const float* mapping   = (const float*)d_in[6];
    const float* samelb    = (const float*)d_in[7];
    const int*   edge      = (const int*)d_in[8];
    const float* W0 = (const float*)d_in[9];
    const float* b0 = (const float*)d_in[10];
    const float* W1 = (const float*)d_in[11];
    const float* b1 = (const float*)d_in[12];
    const float* W2 = (const float*)d_in[13];
    const float* b2 = (const float*)d_in[14];
    const float* W3 = (const float*)d_in[15];
    const float* b3 = (const float*)d_in[16];
    float* out = (float*)d_out;

    k_prep<<<dim3(Bn, 8), 256>>>(attention);
    k_fused<<<dim3(NCHUNK + 3, Bn), 256>>>(attention, mapping, samelb,
                                           coords, upd, nm, edge, c_hs, c_valid,
                                           W0, b0, W1, b1, W2, b2, W3, b3, out);
    k_final<<<1, 128>>>(out);
}